// round 1
// baseline (speedup 1.0000x reference)
#include <cuda_runtime.h>
#include <cstdint>

#define BATCH 32768
#define EMB   256
#define NVEC  4096
#define KNN   20

#define BM 64
#define BN 128
#define AS_STRIDE 68    // 64 + 4 pad (keeps 16B alignment, breaks store conflicts)
#define BS_STRIDE 132   // 128 + 4 pad
#define SMEM_FLOATS (EMB*AS_STRIDE + EMB*BS_STRIDE)
#define SMEM_BYTES  (SMEM_FLOATS * 4)

// scratch: argmin index per batch row (device global => no allocation)
__device__ int g_ix[BATCH];

// ---------------------------------------------------------------------------
// packed f32x2 helpers (sm_100+ packed FP32 pipe: 2 FMAs per instruction)
// ---------------------------------------------------------------------------
__device__ __forceinline__ uint64_t dup_f32(float v) {
    uint64_t r;
    asm("mov.b64 %0, {%1, %1};" : "=l"(r) : "f"(v));
    return r;
}
__device__ __forceinline__ void ffma2(uint64_t& d, uint64_t a, uint64_t b) {
    asm("fma.rn.f32x2 %0, %1, %2, %0;" : "+l"(d) : "l"(a), "l"(b));
}
__device__ __forceinline__ float2 unpack_f32x2(uint64_t v) {
    float2 r;
    asm("mov.b64 {%0, %1}, %2;" : "=f"(r.x), "=f"(r.y) : "l"(v));
    return r;
}

// ---------------------------------------------------------------------------
// Kernel A: fused fp32 GEMM (x . W^T) + per-row argmin.
// Block: 256 threads = 32 (tx) x 8 (ty). Tile: BM=64 rows x BN=128 cols.
// Per-thread microtile: 8 rows (as 4 f32x2 row-pairs) x 4 cols.
// A tile [64 rows x 256 K] resident in SMEM for the whole block; B streamed.
// ---------------------------------------------------------------------------
extern __shared__ float smem[];

__global__ void __launch_bounds__(256, 1)
gemm_argmin_kernel(const float* __restrict__ x, const float* __restrict__ W) {
    float* As = smem;                       // [EMB][AS_STRIDE], As[k*68 + m]
    float* Bs = smem + EMB * AS_STRIDE;     // [EMB][BS_STRIDE], Bs[k*132 + n]

    const int tid = threadIdx.x;
    const int tx  = tid & 31;   // 0..31 -> cols tx*4
    const int ty  = tid >> 5;   // 0..7  -> rows ty*8
    const int m0  = blockIdx.x * BM;

    // ---- load A tile (x rows m0..m0+63, all 256 K), transposed to [k][m] ----
    {
        const float4* x4 = (const float4*)(x + (size_t)m0 * EMB);
        #pragma unroll
        for (int i = 0; i < 16; i++) {              // 64*64 float4 / 256 thr
            int idx = tid + i * 256;
            int row = idx >> 6;                     // 0..63
            int c4  = idx & 63;                     // float4 idx along K
            float4 v = x4[row * 64 + c4];
            int k = c4 * 4;
            As[(k + 0) * AS_STRIDE + row] = v.x;
            As[(k + 1) * AS_STRIDE + row] = v.y;
            As[(k + 2) * AS_STRIDE + row] = v.z;
            As[(k + 3) * AS_STRIDE + row] = v.w;
        }
    }

    float minv[8];
    int   mini[8];
    #pragma unroll
    for (int r = 0; r < 8; r++) { minv[r] = 3.4e38f; mini[r] = 0; }

    for (int n0 = 0; n0 < NVEC; n0 += BN) {
        __syncthreads();    // A ready (iter 0) / previous Bs reads done
        // ---- load B tile (W rows n0..n0+127, all 256 K), transposed ----
        {
            const float4* w4 = (const float4*)(W + (size_t)n0 * EMB);
            #pragma unroll
            for (int i = 0; i < 32; i++) {          // 128*64 float4 / 256 thr
                int idx = tid + i * 256;
                int row = idx >> 6;                 // 0..127 (n within tile)
                int c4  = idx & 63;
                float4 v = w4[row * 64 + c4];
                int k = c4 * 4;
                Bs[(k + 0) * BS_STRIDE + row] = v.x;
                Bs[(k + 1) * BS_STRIDE + row] = v.y;
                Bs[(k + 2) * BS_STRIDE + row] = v.z;
                Bs[(k + 3) * BS_STRIDE + row] = v.w;
            }
        }
        __syncthreads();

        uint64_t acc[4][4];                         // [row-pair][col] f32x2
        #pragma unroll
        for (int p = 0; p < 4; p++)
            #pragma unroll
            for (int j = 0; j < 4; j++) acc[p][j] = 0ull;

        #pragma unroll 4
        for (int kk = 0; kk < EMB; kk++) {
            // A: 8 consecutive row values -> 4 f32x2 pairs, direct 128b loads
            const float* arow = &As[kk * AS_STRIDE + ty * 8];
            ulonglong2 A01 = *(const ulonglong2*)(arow);
            ulonglong2 A23 = *(const ulonglong2*)(arow + 4);
            // B: 4 col values, each duplicated into both f32x2 lanes
            float4 b = *(const float4*)&Bs[kk * BS_STRIDE + tx * 4];
            uint64_t b0 = dup_f32(b.x), b1 = dup_f32(b.y);
            uint64_t b2 = dup_f32(b.z), b3 = dup_f32(b.w);

            ffma2(acc[0][0], A01.x, b0); ffma2(acc[0][1], A01.x, b1);
            ffma2(acc[0][2], A01.x, b2); ffma2(acc[0][3], A01.x, b3);
            ffma2(acc[1][0], A01.y, b0); ffma2(acc[1][1], A01.y, b1);
            ffma2(acc[1][2], A01.y, b2); ffma2(acc[1][3], A01.y, b3);
            ffma2(acc[2][0], A23.x, b0); ffma2(acc[2][1], A23.x, b1);
            ffma2(acc[2][2], A23.x, b2); ffma2(acc[2][3], A23.x, b3);
            ffma2(acc[3][0], A23.y, b0); ffma2(acc[3][1], A23.y, b1);
            ffma2(acc[3][2], A23.y, b2); ffma2(acc[3][3], A23.y, b3);
        }

        // ---- fused argmin update (strict < keeps lowest index: n ascends) ----
        #pragma unroll
        for (int p = 0; p < 4; p++) {
            #pragma unroll
            for (int j = 0; j < 4; j++) {
                float2 v = unpack_f32x2(acc[p][j]);
                int n = n0 + tx * 4 + j;
                if (v.x < minv[2 * p])     { minv[2 * p]     = v.x; mini[2 * p]     = n; }
                if (v.y < minv[2 * p + 1]) { minv[2 * p + 1] = v.y; mini[2 * p + 1] = n; }
            }
        }
    }

    // ---- cross-thread reduction: 32 tx candidates per row ----
    __syncthreads();
    float* sVal = smem;                       // [64][32]
    int*   sIdx = (int*)(smem + 64 * 32);     // [64][32]
    #pragma unroll
    for (int r = 0; r < 8; r++) {
        int row = ty * 8 + r;
        sVal[row * 32 + tx] = minv[r];
        sIdx[row * 32 + tx] = mini[r];
    }
    __syncthreads();
    if (tid < 64) {
        float bv = sVal[tid * 32];
        int   bi = sIdx[tid * 32];
        #pragma unroll
        for (int t = 1; t < 32; t++) {
            float v = sVal[tid * 32 + t];
            int   q = sIdx[tid * 32 + t];
            if (v < bv || (v == bv && q < bi)) { bv = v; bi = q; }
        }
        g_ix[m0 + tid] = bi;
    }
}

// ---------------------------------------------------------------------------
// Kernel B: Gaussian-weighted neighbor gather. One warp per batch row.
// out[b] = sum_{o=-20..20, valid} exp(-o^2/2) * W[ix+o]  /  sum(valid weights)
// valid: 0 <= ix+o < N, and when ix < 20 the o == +20 tap is excluded.
// ---------------------------------------------------------------------------
__global__ void __launch_bounds__(256)
wknn_gather_kernel(const float* __restrict__ W, float* __restrict__ out) {
    const int lane = threadIdx.x & 31;
    const int warp = threadIdx.x >> 5;
    const int b    = blockIdx.x * 8 + warp;

    const int ix = g_ix[b];
    const bool left_edge = (ix < KNN);

    float4 a0 = {0.f, 0.f, 0.f, 0.f};
    float4 a1 = {0.f, 0.f, 0.f, 0.f};
    float wsum = 0.f;

    #pragma unroll
    for (int j = 0; j <= 2 * KNN; j++) {
        const int o = j - KNN;
        const int idx = ix + o;
        bool valid = (idx >= 0) && (idx < NVEC) && !(left_edge && (o == KNN));
        if (valid) {
            const float g = expf(-0.5f * (float)(o * o));   // const-folded
            wsum += g;
            const float4* wr = (const float4*)(W + (size_t)idx * EMB) + lane * 2;
            float4 v0 = wr[0];
            float4 v1 = wr[1];
            a0.x += g * v0.x; a0.y += g * v0.y; a0.z += g * v0.z; a0.w += g * v0.w;
            a1.x += g * v1.x; a1.y += g * v1.y; a1.z += g * v1.z; a1.w += g * v1.w;
        }
    }

    const float inv = 1.0f / wsum;
    a0.x *= inv; a0.y *= inv; a0.z *= inv; a0.w *= inv;
    a1.x *= inv; a1.y *= inv; a1.z *= inv; a1.w *= inv;

    float4* op = (float4*)(out + (size_t)b * EMB) + lane * 2;
    op[0] = a0;
    op[1] = a1;
}

// ---------------------------------------------------------------------------
extern "C" void kernel_launch(void* const* d_in, const int* in_sizes, int n_in,
                              void* d_out, int out_size) {
    // metadata order: x [32768*256], W [4096*256] — guard by size anyway
    const float* x;
    const float* W;
    if (in_sizes[0] == BATCH * EMB) { x = (const float*)d_in[0]; W = (const float*)d_in[1]; }
    else                            { x = (const float*)d_in[1]; W = (const float*)d_in[0]; }
    float* out = (float*)d_out;

    cudaFuncSetAttribute(gemm_argmin_kernel,
                         cudaFuncAttributeMaxDynamicSharedMemorySize, SMEM_BYTES);

    gemm_argmin_kernel<<<BATCH / BM, 256, SMEM_BYTES>>>(x, W);
    wknn_gather_kernel<<<BATCH / 8, 256>>>(W, out);
}

// round 7
// speedup vs baseline: 2.7682x; 2.7682x over previous
#include <cuda_runtime.h>
#include <cuda_fp16.h>
#include <cstdint>

#define BATCH 32768
#define EMB   256
#define NVEC  4096
#define KNN   20
#define TAU   0.05f

#define M_TILE 128
#define BN     64            // N chunk
#define KC     64            // K chunk (halves)
#define N_CHUNKS (NVEC / BN)           // 64
#define K_CHUNKS (EMB / KC)            // 4
#define STAGES   (N_CHUNKS * K_CHUNKS) // 256

#define STRIDE_A 264         // halves per A row
#define STRIDE_B 72          // halves per B row

// smem offsets (bytes)
#define OFF_AH 0
#define OFF_AL (M_TILE * STRIDE_A * 2)
#define OFF_B  (2 * M_TILE * STRIDE_A * 2)
#define BBUF_SZ (2 * BN * STRIDE_B * 2)
#define OFF_BH(buf) (OFF_B + (buf) * BBUF_SZ)
#define OFF_BL(buf) (OFF_BH(buf) + BN * STRIDE_B * 2)
#define SMEM_BYTES (OFF_B + 2 * BBUF_SZ)

// device scratch
__device__ float  g_dist[(size_t)BATCH * NVEC];   // 512 MB approx distances
__device__ int    g_ix[BATCH];
__device__ int    g_nflag;
__device__ int    g_list[BATCH];
__device__ __half gXh[BATCH * EMB];
__device__ __half gXl[BATCH * EMB];
__device__ __half gWh[NVEC * EMB];
__device__ __half gWl[NVEC * EMB];

// ---------------------------------------------------------------------------
__device__ __forceinline__ uint32_t smem_u32(const void* p) {
    uint32_t a;
    asm("{ .reg .u64 t; cvta.to.shared.u64 t, %1; cvt.u32.u64 %0, t; }" : "=r"(a) : "l"(p));
    return a;
}
#define CP_ASYNC16(dst, src) \
    asm volatile("cp.async.cg.shared.global [%0], [%1], 16;" :: "r"(dst), "l"(src) : "memory")
#define CP_COMMIT() asm volatile("cp.async.commit_group;" ::: "memory")
#define CP_WAIT1()  asm volatile("cp.async.wait_group 1;" ::: "memory")
#define CP_WAIT0()  asm volatile("cp.async.wait_group 0;" ::: "memory")

#define LDMATRIX_X4(r0, r1, r2, r3, a) \
    asm volatile("ldmatrix.sync.aligned.m8n8.x4.shared.b16 {%0,%1,%2,%3}, [%4];" \
                 : "=r"(r0), "=r"(r1), "=r"(r2), "=r"(r3) : "r"(a))

#define MMA16816(c, a0, a1, a2, a3, b0, b1)                                      \
    asm volatile("mma.sync.aligned.m16n8k16.row.col.f32.f16.f16.f32 "            \
                 "{%0,%1,%2,%3}, {%4,%5,%6,%7}, {%8,%9}, {%0,%1,%2,%3};"         \
                 : "+f"((c)[0]), "+f"((c)[1]), "+f"((c)[2]), "+f"((c)[3])        \
                 : "r"(a0), "r"(a1), "r"(a2), "r"(a3), "r"(b0), "r"(b1))

// ordering with index tie-break (lowest index wins on equal value)
__device__ __forceinline__ bool lt2(float v, int i, float w, int j) {
    return v < w || (v == w && i < j);
}
__device__ __forceinline__ void upd2(float v, int n, float& v1, int& i1,
                                     float& v2, int& i2) {
    if (lt2(v, n, v1, i1)) { v2 = v1; i2 = i1; v1 = v; i1 = n; }
    else if (lt2(v, n, v2, i2)) { v2 = v; i2 = n; }
}
__device__ __forceinline__ void merge2(float b1, int bi1, float b2, int bi2,
                                       float& a1, int& ai1, float& a2, int& ai2) {
    if (lt2(b1, bi1, a1, ai1)) {
        float n2; int n2i;
        if (lt2(a1, ai1, b2, bi2)) { n2 = a1; n2i = ai1; } else { n2 = b2; n2i = bi2; }
        a1 = b1; ai1 = bi1; a2 = n2; ai2 = n2i;
    } else if (lt2(b1, bi1, a2, ai2)) {
        a2 = b1; ai2 = bi1;
    }
}

// authoritative distance: STRICTLY SEQUENTIAL fp32 FMA over k=0..255 with a
// single accumulator — bitwise-identical to the R1 kernel that matched the
// reference argmin on every row. The fmaf dependence chain forbids
// reassociation; unrolling only batches the loads.
__device__ __forceinline__ float seqdot(const float* __restrict__ xr,
                                        const float* __restrict__ wr) {
    float d = 0.f;
    #pragma unroll 8
    for (int k = 0; k < EMB; k++) d = fmaf(xr[k], wr[k], d);
    return d;
}

// ---------------------------------------------------------------------------
// Kernel R: reset flag counter
// ---------------------------------------------------------------------------
__global__ void reset_kernel() {
    if (threadIdx.x == 0) g_nflag = 0;
}

// ---------------------------------------------------------------------------
// Kernel 0: fp16 hi/lo split of x and W
// ---------------------------------------------------------------------------
__global__ void __launch_bounds__(256)
split_fp16_kernel(const float* __restrict__ x, const float* __restrict__ W) {
    int t = blockIdx.x * blockDim.x + threadIdx.x;
    int stride = gridDim.x * blockDim.x;
    const float4* x4 = (const float4*)x;
    const float4* w4 = (const float4*)W;
    for (int i = t; i < BATCH * EMB / 4; i += stride) {
        float4 v = x4[i];
        __half h0 = __float2half_rn(v.x), h1 = __float2half_rn(v.y);
        __half h2 = __float2half_rn(v.z), h3 = __float2half_rn(v.w);
        __half l0 = __float2half_rn(v.x - __half2float(h0));
        __half l1 = __float2half_rn(v.y - __half2float(h1));
        __half l2 = __float2half_rn(v.z - __half2float(h2));
        __half l3 = __float2half_rn(v.w - __half2float(h3));
        ((__half2*)gXh)[i * 2]     = __halves2half2(h0, h1);
        ((__half2*)gXh)[i * 2 + 1] = __halves2half2(h2, h3);
        ((__half2*)gXl)[i * 2]     = __halves2half2(l0, l1);
        ((__half2*)gXl)[i * 2 + 1] = __halves2half2(l2, l3);
    }
    for (int i = t; i < NVEC * EMB / 4; i += stride) {
        float4 v = w4[i];
        __half h0 = __float2half_rn(v.x), h1 = __float2half_rn(v.y);
        __half h2 = __float2half_rn(v.z), h3 = __float2half_rn(v.w);
        __half l0 = __float2half_rn(v.x - __half2float(h0));
        __half l1 = __float2half_rn(v.y - __half2float(h1));
        __half l2 = __float2half_rn(v.z - __half2float(h2));
        __half l3 = __float2half_rn(v.w - __half2float(h3));
        ((__half2*)gWh)[i * 2]     = __halves2half2(h0, h1);
        ((__half2*)gWh)[i * 2 + 1] = __halves2half2(h2, h3);
        ((__half2*)gWl)[i * 2]     = __halves2half2(l0, l1);
        ((__half2*)gWl)[i * 2 + 1] = __halves2half2(l2, l3);
    }
}

// ---------------------------------------------------------------------------
// Kernel 1: fp16 split-GEMM (dist = x . W^T), stores full dist matrix.
// ---------------------------------------------------------------------------
extern __shared__ char dsm[];

__global__ void __launch_bounds__(256, 1)
gemm_store_kernel() {
    const int tid  = threadIdx.x;
    const int lane = tid & 31;
    const int wid  = tid >> 5;
    const int wm   = wid >> 1;          // 0..3
    const int wn   = wid & 1;           // 0..1
    const int m0   = blockIdx.x * M_TILE;

    const uint32_t sb = smem_u32(dsm);

    // ---- resident A load (hi+lo, 128 rows x 256 halves) ----
    #pragma unroll
    for (int i = 0; i < 16; i++) {
        int idx = tid + i * 256;
        int row = idx >> 5, seg = idx & 31;
        uint32_t off = (uint32_t)(row * STRIDE_A + seg * 8) * 2;
        CP_ASYNC16(sb + OFF_AH + off, gXh + (size_t)(m0 + row) * EMB + seg * 8);
        CP_ASYNC16(sb + OFF_AL + off, gXl + (size_t)(m0 + row) * EMB + seg * 8);
    }
    // ---- prefetch stage 0 B ----
    #pragma unroll
    for (int i = 0; i < 2; i++) {
        int idx = tid + i * 256;
        int row = idx >> 3, seg = idx & 7;
        uint32_t off = (uint32_t)(row * STRIDE_B + seg * 8) * 2;
        CP_ASYNC16(sb + OFF_BH(0) + off, gWh + (size_t)row * EMB + seg * 8);
        CP_ASYNC16(sb + OFF_BL(0) + off, gWl + (size_t)row * EMB + seg * 8);
    }
    CP_COMMIT();

    const int arow  = (lane & 7) + ((lane >> 3) & 1) * 8;
    const int akoff = (lane >> 4) * 8;
    const int brow  = (lane & 7) + (lane >> 4) * 8;
    const int bkoff = ((lane >> 3) & 1) * 8;

    float acc[2][4][4];

    for (int s = 0; s < STAGES; s++) {
        const int nc = s >> 2, kc = s & 3;
        const int buf = s & 1;

        if (s + 1 < STAGES) {
            const int nn = (s + 1) >> 2, nk = (s + 1) & 3;
            const int nb = (s + 1) & 1;
            #pragma unroll
            for (int i = 0; i < 2; i++) {
                int idx = tid + i * 256;
                int row = idx >> 3, seg = idx & 7;
                uint32_t off = (uint32_t)(row * STRIDE_B + seg * 8) * 2;
                const size_t src = (size_t)(nn * BN + row) * EMB + nk * KC + seg * 8;
                CP_ASYNC16(sb + OFF_BH(nb) + off, gWh + src);
                CP_ASYNC16(sb + OFF_BL(nb) + off, gWl + src);
            }
            CP_COMMIT();
            CP_WAIT1();
        } else {
            CP_WAIT0();
        }
        __syncthreads();

        if (kc == 0) {
            #pragma unroll
            for (int mf = 0; mf < 2; mf++)
                #pragma unroll
                for (int nf = 0; nf < 4; nf++)
                    #pragma unroll
                    for (int j = 0; j < 4; j++) acc[mf][nf][j] = 0.f;
        }

        #pragma unroll
        for (int k16 = 0; k16 < 4; k16++) {
            const int kgA = kc * KC + k16 * 16;
            uint32_t ah[2][4], al[2][4], bh[2][4], bl[2][4];
            #pragma unroll
            for (int mf = 0; mf < 2; mf++) {
                uint32_t aoff = (uint32_t)((wm * 32 + mf * 16 + arow) * STRIDE_A
                                           + kgA + akoff) * 2;
                LDMATRIX_X4(ah[mf][0], ah[mf][1], ah[mf][2], ah[mf][3], sb + OFF_AH + aoff);
                LDMATRIX_X4(al[mf][0], al[mf][1], al[mf][2], al[mf][3], sb + OFF_AL + aoff);
            }
            #pragma unroll
            for (int g = 0; g < 2; g++) {
                uint32_t boff = (uint32_t)((wn * 32 + g * 16 + brow) * STRIDE_B
                                           + k16 * 16 + bkoff) * 2;
                LDMATRIX_X4(bh[g][0], bh[g][1], bh[g][2], bh[g][3], sb + OFF_BH(buf) + boff);
                LDMATRIX_X4(bl[g][0], bl[g][1], bl[g][2], bl[g][3], sb + OFF_BL(buf) + boff);
            }
            #pragma unroll
            for (int mf = 0; mf < 2; mf++) {
                #pragma unroll
                for (int nf = 0; nf < 4; nf++) {
                    const int g = nf >> 1, h = (nf & 1) * 2;
                    MMA16816(acc[mf][nf], ah[mf][0], ah[mf][1], ah[mf][2], ah[mf][3],
                             bh[g][h], bh[g][h + 1]);
                    MMA16816(acc[mf][nf], ah[mf][0], ah[mf][1], ah[mf][2], ah[mf][3],
                             bl[g][h], bl[g][h + 1]);
                    MMA16816(acc[mf][nf], al[mf][0], al[mf][1], al[mf][2], al[mf][3],
                             bh[g][h], bh[g][h + 1]);
                }
            }
        }

        // ---- N-chunk done: store the 64-wide dist slab ----
        if (kc == 3) {
            const int nb0 = nc * BN + wn * 32 + (lane & 3) * 2;
            #pragma unroll
            for (int mf = 0; mf < 2; mf++) {
                #pragma unroll
                for (int half = 0; half < 2; half++) {
                    const int row = m0 + wm * 32 + mf * 16 + half * 8 + (lane >> 2);
                    float* dp = g_dist + (size_t)row * NVEC + nb0;
                    #pragma unroll
                    for (int nf = 0; nf < 4; nf++) {
                        float2 v;
                        v.x = acc[mf][nf][half * 2];
                        v.y = acc[mf][nf][half * 2 + 1];
                        *(float2*)(dp + nf * 8) = v;
                    }
                }
            }
        }
        __syncthreads();   // protect B buffer reuse
    }
}

// ---------------------------------------------------------------------------
// Kernel 2: select. Warp/row: positional top-2 over stored dist row, then
// AUTHORITATIVE sequential-FMA rescore of both candidates; flag row for full
// scan if the stored value at the claimed min is inconsistent.
// ---------------------------------------------------------------------------
__global__ void __launch_bounds__(256)
select_kernel(const float* __restrict__ x, const float* __restrict__ W) {
    const int lane = threadIdx.x & 31;
    const int warp = threadIdx.x >> 5;
    const int b    = blockIdx.x * 8 + warp;

    // per-lane top-2 over the stored row
    float v1 = 3.4e38f, v2 = 3.4e38f;
    int   i1 = 0x7FFFFFFF, i2 = 0x7FFFFFFF;
    const float4* dr = (const float4*)(g_dist + (size_t)b * NVEC);
    #pragma unroll 4
    for (int it = 0; it < NVEC / 128; it++) {       // 32 iters
        float4 v = dr[it * 32 + lane];
        int n = (it * 32 + lane) * 4;
        upd2(v.x, n,     v1, i1, v2, i2);
        upd2(v.y, n + 1, v1, i1, v2, i2);
        upd2(v.z, n + 2, v1, i1, v2, i2);
        upd2(v.w, n + 3, v1, i1, v2, i2);
    }
    #pragma unroll
    for (int d = 1; d < 32; d <<= 1) {
        float ov1 = __shfl_xor_sync(0xFFFFFFFF, v1, d);
        int   oi1 = __shfl_xor_sync(0xFFFFFFFF, i1, d);
        float ov2 = __shfl_xor_sync(0xFFFFFFFF, v2, d);
        int   oi2 = __shfl_xor_sync(0xFFFFFFFF, i2, d);
        merge2(ov1, oi1, ov2, oi2, v1, i1, v2, i2);
    }

    // authoritative sequential rescore: lane 0 -> i1, lane 1 -> i2
    const int cand = (lane == 0) ? i1 : i2;
    float dseq = 0.f;
    if (lane < 2)
        dseq = seqdot(x + (size_t)b * EMB, W + (size_t)cand * EMB);
    float d1 = __shfl_sync(0xFFFFFFFF, dseq, 0);
    float d2 = __shfl_sync(0xFFFFFFFF, dseq, 1);

    if (lane == 0) {
        g_ix[b] = lt2(d2, i2, d1, i1) ? i2 : i1;
        // consistency: stored approx at the claimed min must match exact
        if (fabsf(d1 - v1) > TAU) {
            int pos = atomicAdd(&g_nflag, 1);
            g_list[pos] = b;
        }
    }
}

// ---------------------------------------------------------------------------
// Kernel 3: full sequential-FMA argmin scan for flagged rows.
// ---------------------------------------------------------------------------
__global__ void __launch_bounds__(256)
fullscan_kernel(const float* __restrict__ x, const float* __restrict__ W) {
    __shared__ float sx[EMB];
    __shared__ float sval[256];
    __shared__ int   sidx[256];
    const int tid = threadIdx.x;

    for (int j = blockIdx.x; j < g_nflag; j += gridDim.x) {
        const int b = g_list[j];
        if (tid < EMB) sx[tid] = x[(size_t)b * EMB + tid];
        __syncthreads();

        float bv = 3.4e38f;
        int   bi = 0x7FFFFFFF;
        for (int n = tid; n < NVEC; n += 256) {
            float d = seqdot(sx, W + (size_t)n * EMB);
            if (lt2(d, n, bv, bi)) { bv = d; bi = n; }
        }
        sval[tid] = bv; sidx[tid] = bi;
        __syncthreads();
        for (int st = 128; st; st >>= 1) {
            if (tid < st) {
                if (lt2(sval[tid + st], sidx[tid + st], sval[tid], sidx[tid])) {
                    sval[tid] = sval[tid + st]; sidx[tid] = sidx[tid + st];
                }
            }
            __syncthreads();
        }
        if (tid == 0) g_ix[b] = sidx[0];
        __syncthreads();
    }
}

// ---------------------------------------------------------------------------
// Kernel 4: Gaussian-weighted neighbor gather. One warp per batch row.
// ---------------------------------------------------------------------------
__global__ void __launch_bounds__(256)
wknn_gather_kernel(const float* __restrict__ W, float* __restrict__ out) {
    const int lane = threadIdx.x & 31;
    const int warp = threadIdx.x >> 5;
    const int b    = blockIdx.x * 8 + warp;

    const int ix = g_ix[b];
    const bool left_edge = (ix < KNN);

    float4 a0 = {0.f, 0.f, 0.f, 0.f};
    float4 a1 = {0.f, 0.f, 0.f, 0.f};
    float wsum = 0.f;

    #pragma unroll
    for (int j = 0; j <= 2 * KNN; j++) {
        const int o = j - KNN;
        const int idx = ix + o;
        bool valid = (idx >= 0) && (idx < NVEC) && !(left_edge && (o == KNN));
        if (valid) {
            const float g = expf(-0.5f * (float)(o * o));
            wsum += g;
            const float4* wr = (const float4*)(W + (size_t)idx * EMB) + lane * 2;
            float4 v0 = wr[0];
            float4 v1 = wr[1];
            a0.x += g * v0.x; a0.y += g * v0.y; a0.z += g * v0.z; a0.w += g * v0.w;
            a1.x += g * v1.x; a1.y += g * v1.y; a1.z += g * v1.z; a1.w += g * v1.w;
        }
    }

    const float inv = 1.0f / wsum;
    a0.x *= inv; a0.y *= inv; a0.z *= inv; a0.w *= inv;
    a1.x *= inv; a1.y *= inv; a1.z *= inv; a1.w *= inv;

    float4* op = (float4*)(out + (size_t)b * EMB) + lane * 2;
    op[0] = a0;
    op[1] = a1;
}

// ---------------------------------------------------------------------------
extern "C" void kernel_launch(void* const* d_in, const int* in_sizes, int n_in,
                              void* d_out, int out_size) {
    const float* x;
    const float* W;
    if (in_sizes[0] == BATCH * EMB) { x = (const float*)d_in[0]; W = (const float*)d_in[1]; }
    else                            { x = (const float*)d_in[1]; W = (const float*)d_in[0]; }
    float* out = (float*)d_out;

    cudaFuncSetAttribute(gemm_store_kernel,
                         cudaFuncAttributeMaxDynamicSharedMemorySize, SMEM_BYTES);

    reset_kernel<<<1, 32>>>();
    split_fp16_kernel<<<2048, 256>>>(x, W);
    gemm_store_kernel<<<BATCH / M_TILE, 256, SMEM_BYTES>>>();
    select_kernel<<<BATCH / 8, 256>>>(x, W);
    fullscan_kernel<<<64, 256>>>(x, W);
    wknn_gather_kernel<<<BATCH / 8, 256>>>(W, out);
}